// round 16
// baseline (speedup 1.0000x reference)
#include <cuda_runtime.h>
#include <cuda_fp16.h>
#include <math.h>

#define NU 100000
#define NI 50000
#define NE 120000
#define NR 32
#define DM 64
#define NEDGE 1000000
#define NCF 1000000

#define SEG_U 120000
#define SEG_I 220000
#define NSEG 270000
#define SCAN_N 270001
#define SCAN_BLK 1024
#define SCAN_NBLK 264

#define USER_BLOCKS 12500         // NU/8
#define ITEM_BLOCKS 6250          // NI/8

__device__ int   g_cnt[SCAN_NBLK * SCAN_BLK];
__device__ int   g_off[SCAN_NBLK * SCAN_BLK + 1];
__device__ int   g_perm[NEDGE + 2 * NCF];   // PAYLOADS: entity=(tail<<5)|type, user=col, item=row
__device__ int   g_bsum[SCAN_BLK];

__device__ float g_entA[NE * DM];
__device__ float g_entB[NE * DM];
__device__ float g_u[NU * DM];
__device__ float g_ucf0[NU * DM];
__device__ float g_ucf1[NU * DM];
__device__ float g_p[NCF];
__device__ float g_pcf[NCF];

// transposed weight matrices (Wt[k*64+d] = W[d*64+k]), per hop
__device__ float g_W1t[2][DM * DM];
__device__ float g_W2t[2][DM * DM];

// half item tables gathered by k_useritem (col < NI only); icf double-buffered
__device__ __half g_relkg_h[NI * DM];
__device__ __half g_kg_h[NI * DM];
__device__ __half g_icf_h[2][NI * DM];

__device__ __forceinline__ float warpsum(float v) {
    #pragma unroll
    for (int o = 16; o; o >>= 1) v += __shfl_xor_sync(0xffffffffu, v, o);
    return v;
}
__device__ __forceinline__ float lrelu(float x) { return x > 0.f ? x : 0.01f * x; }
__device__ __forceinline__ float sigmoidf(float x) { return 1.f / (1.f + __expf(-x)); }

// init: out = concat(...) + zero counters + seed icf_h[0] + transpose weights
__global__ void k_init(const float* __restrict__ ue, const float* __restrict__ ee,
                       const float* __restrict__ cf,
                       const float* __restrict__ W1, const float* __restrict__ W2,
                       float* __restrict__ out) {
    const int total = (NE + NU + NU + NI) * DM;
    for (int i = blockIdx.x * blockDim.x + threadIdx.x; i < total; i += gridDim.x * blockDim.x) {
        if (i < SCAN_NBLK * SCAN_BLK) g_cnt[i] = 0;
        if (i < 2 * DM * DM) {              // transpose both hops' W1/W2
            int h = i >> 12, r = i & 4095;
            int d = r >> 6, k = r & 63;
            g_W1t[h][k * 64 + d] = W1[h * 4096 + d * 64 + k];
            g_W2t[h][k * 64 + d] = W2[h * 4096 + d * 64 + k];
        }
        float v;
        if (i < NE * DM)                   v = ee[i];
        else if (i < (NE + NU) * DM)       v = ue[i - NE * DM];
        else if (i < (NE + 2 * NU) * DM)   v = cf[i - (NE + NU) * DM];
        else {
            int d = i - (NE + 2 * NU) * DM;
            v = cf[NU * DM + d];
            g_icf_h[0][d] = __float2half(v);
        }
        out[i] = v;
    }
}

__global__ void k_count(const int* __restrict__ heads, const int2* __restrict__ imat2) {
    for (int i = blockIdx.x * blockDim.x + threadIdx.x; i < NEDGE; i += gridDim.x * blockDim.x) {
        int2 rc = imat2[i];
        atomicAdd(&g_cnt[heads[i]], 1);
        atomicAdd(&g_cnt[SEG_U + rc.x], 1);
        atomicAdd(&g_cnt[SEG_I + rc.y], 1);
    }
}

__global__ void k_scan1() {
    __shared__ int sh[SCAN_BLK];
    int t = threadIdx.x;
    int i = blockIdx.x * SCAN_BLK + t;
    sh[t] = (i < SCAN_N) ? g_cnt[i] : 0;
    __syncthreads();
    for (int s = SCAN_BLK / 2; s > 0; s >>= 1) {
        if (t < s) sh[t] += sh[t + s];
        __syncthreads();
    }
    if (t == 0) g_bsum[blockIdx.x] = sh[0];
}

// fused scan2+scan3
__global__ void k_scanB() {
    __shared__ int sb[SCAN_BLK];
    __shared__ int sh[SCAN_BLK];
    int t = threadIdx.x;
    int v0 = (t < SCAN_NBLK) ? g_bsum[t] : 0;
    sb[t] = v0;
    __syncthreads();
    for (int d = 1; d < SCAN_BLK; d <<= 1) {
        int x = (t >= d) ? sb[t - d] : 0;
        __syncthreads();
        sb[t] += x;
        __syncthreads();
    }
    int boff = (blockIdx.x == 0) ? 0 : sb[blockIdx.x - 1];

    int i = blockIdx.x * SCAN_BLK + t;
    int v = (i < SCAN_N) ? g_cnt[i] : 0;
    sh[t] = v;
    __syncthreads();
    for (int d = 1; d < SCAN_BLK; d <<= 1) {
        int x = (t >= d) ? sh[t - d] : 0;
        __syncthreads();
        sh[t] += x;
        __syncthreads();
    }
    if (i < SCAN_N) g_off[i] = boff + sh[t] - v;
}

// in-place cursors: atomicAdd on g_off[seg] hands out slots directly.
// Post-scatter invariant: g_off[s] == original off[s+1]  (end of segment s).
// Consumers read p1 = g_off[s], p0 = s ? g_off[s-1] : 0.
__global__ void k_scatter(const int* __restrict__ heads, const int* __restrict__ tails,
                          const int* __restrict__ etype, const int2* __restrict__ imat2) {
    for (int i = blockIdx.x * blockDim.x + threadIdx.x; i < NEDGE; i += gridDim.x * blockDim.x) {
        int h = heads[i];
        int p = atomicAdd(&g_off[h], 1);
        g_perm[p] = (tails[i] << 5) | etype[i];
        int2 rc = imat2[i];
        p = atomicAdd(&g_off[SEG_U + rc.x], 1);
        g_perm[p] = rc.y;
        p = atomicAdd(&g_off[SEG_I + rc.y], 1);
        g_perm[p] = rc.x;
    }
}

// entity aggregation: warp-per-entity, LOW-SMEM (s_rel only, 8KB -> full occupancy).
// Matvec reads transposed weights from global (L1-resident, coalesced per k).
__global__ void k_entity(const float* __restrict__ ext_ent, int hop,
                         const float* __restrict__ relw,
                         const float* __restrict__ b1, const float* __restrict__ b2,
                         float* __restrict__ out) {
    __shared__ float s_rel[NR * DM];
    int t = threadIdx.x;
    for (int i = t; i < NR * DM; i += blockDim.x) s_rel[i] = relw[i];
    __syncthreads();

    const float* entin = hop ? g_entB : ext_ent;
    float* entout      = hop ? g_entA : g_entB;
    const float* Wt1 = g_W1t[hop];
    const float* Wt2 = g_W2t[hop];

    int lane = t & 31;
    int e = blockIdx.x * (blockDim.x >> 5) + (t >> 5);
    if (e >= NE) return;
    int p1 = g_off[e];
    int p0 = e ? g_off[e - 1] : 0;
    bool eItem = e < NI;

    float a10 = 0, a11 = 0, a20 = 0, a21 = 0, ar0 = 0, ar1 = 0;
    int nc = 0;
    for (int p = p0; p < p1; p++) {
        int packed = g_perm[p];
        int tl = packed >> 5, ty = packed & 31;
        float r0 = s_rel[ty * 64 + lane], r1 = s_rel[ty * 64 + 32 + lane];
        float t0 = entin[tl * 64 + lane], t1 = entin[tl * 64 + 32 + lane];
        bool cross = eItem != (tl < NI);
        if (cross) { a10 += t0 * r0; a11 += t1 * r1; nc++; }
        else       { a20 += t0 + r0; a21 += t1 + r1; }
        ar0 += r0; ar1 += r1;
    }
    int n = p1 - p0;

    if (eItem) {
        float dn = 1.f / fmaxf((float)n, 1.f);
        float e0 = entin[e * 64 + lane], e1 = entin[e * 64 + 32 + lane];
        g_relkg_h[e * 64 + lane]      = __float2half((ar0 * dn) * e0);
        g_relkg_h[e * 64 + 32 + lane] = __float2half((ar1 * dn) * e1);
        g_kg_h[e * 64 + lane]         = __float2half(e0);
        g_kg_h[e * 64 + 32 + lane]    = __float2half(e1);
    }

    float i1 = 1.f / fmaxf((float)nc, 1.f);
    float i2 = 1.f / fmaxf((float)(n - nc), 1.f);
    a10 *= i1; a11 *= i1; a20 *= i2; a21 *= i2;

    float o10 = __ldg(&b1[lane]), o11 = __ldg(&b1[lane + 32]);
    float o20 = __ldg(&b2[lane]), o21 = __ldg(&b2[lane + 32]);
    #pragma unroll
    for (int k = 0; k < 64; k++) {
        float a1 = __shfl_sync(0xffffffffu, (k < 32) ? a10 : a11, k & 31);
        float a2 = __shfl_sync(0xffffffffu, (k < 32) ? a20 : a21, k & 31);
        o10 += a1 * __ldg(&Wt1[k * 64 + lane]);
        o11 += a1 * __ldg(&Wt1[k * 64 + 32 + lane]);
        o20 += a2 * __ldg(&Wt2[k * 64 + lane]);
        o21 += a2 * __ldg(&Wt2[k * 64 + 32 + lane]);
    }
    float v0 = 0.5f * (lrelu(o10) + lrelu(o20));
    float v1 = 0.5f * (lrelu(o11) + lrelu(o21));
    float ss = warpsum(v0 * v0 + v1 * v1);
    float inv = 1.f / fmaxf(sqrtf(ss), 1e-12f);
    v0 *= inv; v1 *= inv;
    entout[e * 64 + lane] = v0;
    entout[e * 64 + 32 + lane] = v1;
    out[e * 64 + lane] += v0;
    out[e * 64 + 32 + lane] += v1;
}

// fused USER + ITEM kernel (R11/R12-proven; p0/p1 from adjacent g_off entries).
__global__ void __launch_bounds__(256) k_useritem(
        const float* __restrict__ ext_user, const float* __restrict__ ext_ucf,
        int hop, float* __restrict__ out)
{
    __shared__ __align__(16) float sm[8 * 320];   // per warp: U64|UC64|W64|WC64|COL64

    int w = threadIdx.x >> 5, lane = threadIdx.x & 31;

    if (blockIdx.x >= USER_BLOCKS) {
        // ---------------- item path ----------------
        const float2* ucfin2 = (const float2*)(hop ? g_ucf0 : ext_ucf);
        float2* out2 = (float2*)out;
        int c = (blockIdx.x - USER_BLOCKS) * 8 + w;
        if (c >= NI) return;
        int p1 = g_off[SEG_I + c];
        int p0 = g_off[SEG_I + c - 1];
        float2 acc = make_float2(0.f, 0.f);
        for (int p = p0; p < p1; p++) {
            int row = g_perm[p];
            float2 v = ucfin2[row * 32 + lane];
            acc.x += v.x; acc.y += v.y;
        }
        float dn = 1.f / fmaxf((float)(p1 - p0), 1.f);
        acc.x *= dn; acc.y *= dn;
        float ss = warpsum(acc.x * acc.x + acc.y * acc.y);
        float inv = 1.f / fmaxf(sqrtf(ss), 1e-12f);
        acc.x *= inv; acc.y *= inv;
        ((__half2*)g_icf_h[(hop + 1) & 1])[c * 32 + lane] = __floats2half2_rn(acc.x, acc.y);
        int ob = (NE + 2 * NU) * 32 + c * 32 + lane;
        float2 o = out2[ob];
        o.x += acc.x; o.y += acc.y;
        out2[ob] = o;
        return;
    }

    // ---------------- user path ----------------
    const __half* icf_tab = g_icf_h[hop & 1];
    const uint4* rkh4    = (const uint4*)g_relkg_h;
    const uint4* icfh4   = (const uint4*)icf_tab;
    const __half2* rkh2  = (const __half2*)g_relkg_h;
    const __half2* kgh2  = (const __half2*)g_kg_h;
    const __half2* icfh2 = (const __half2*)icf_tab;
    const float* usrc    = hop ? g_u    : ext_user;
    const float* ucfsrc  = hop ? g_ucf0 : ext_ucf;
    float2* udst2   = (float2*)g_u;
    float2* ucfdst2 = (float2*)(hop ? g_ucf1 : g_ucf0);
    float2* out2    = (float2*)out;

    int u = blockIdx.x * 8 + w;
    if (u >= NU) return;

    float* sU  = sm + w * 320;
    float* sUC = sU + 64;
    float* sW  = sU + 128;
    float* sWC = sU + 192;
    int*   sCol = (int*)(sU + 256);

    int p1 = g_off[SEG_U + u];
    int p0 = g_off[SEG_U + u - 1];
    int n  = p1 - p0;
    if (n == 0) {
        float2 z = make_float2(0.f, 0.f);
        udst2[u * 32 + lane] = z;
        ucfdst2[u * 32 + lane] = z;
        return;
    }
    int pb = p0 - NEDGE;
    int nin = n < 64 ? n : 64;

    sU[lane]       = usrc[u * 64 + lane];
    sU[32 + lane]  = usrc[u * 64 + 32 + lane];
    sUC[lane]      = ucfsrc[u * 64 + lane];
    sUC[32 + lane] = ucfsrc[u * 64 + 32 + lane];
    if (lane < nin)      sCol[lane]      = g_perm[p0 + lane];
    if (lane + 32 < nin) sCol[lane + 32] = g_perm[p0 + lane + 32];
    __syncwarp();

    float2 ud, cd;
    int li = lane & 7, g = lane >> 3;

    for (int it = 0; it < 3; it++) {
        // ---- pass 1: dots, 4 pairs per warp (8 lanes each), half rows ----
        for (int jb = 0; jb < nin; jb += 4) {
            int j = jb + g;
            bool act = j < nin;
            int col = act ? sCol[j] : 0;
            uint4 ra = rkh4[col * 8 + li];
            uint4 ba = icfh4[col * 8 + li];
            float2 r0 = __half22float2(*(const __half2*)&ra.x);
            float2 r1 = __half22float2(*(const __half2*)&ra.y);
            float2 r2 = __half22float2(*(const __half2*)&ra.z);
            float2 r3 = __half22float2(*(const __half2*)&ra.w);
            float2 b0 = __half22float2(*(const __half2*)&ba.x);
            float2 b1 = __half22float2(*(const __half2*)&ba.y);
            float2 b2 = __half22float2(*(const __half2*)&ba.z);
            float2 b3 = __half22float2(*(const __half2*)&ba.w);
            float4 u0 = *(const float4*)(sU + 8 * li);
            float4 u1 = *(const float4*)(sU + 8 * li + 4);
            float4 c0 = *(const float4*)(sUC + 8 * li);
            float4 c1 = *(const float4*)(sUC + 8 * li + 4);
            float s  = r0.x*u0.x + r0.y*u0.y + r1.x*u0.z + r1.y*u0.w
                     + r2.x*u1.x + r2.y*u1.y + r3.x*u1.z + r3.y*u1.w;
            float sc = b0.x*c0.x + b0.y*c0.y + b1.x*c0.z + b1.y*c0.w
                     + b2.x*c1.x + b2.y*c1.y + b3.x*c1.z + b3.y*c1.w;
            s  += __shfl_xor_sync(0xffffffffu, s, 1);
            sc += __shfl_xor_sync(0xffffffffu, sc, 1);
            s  += __shfl_xor_sync(0xffffffffu, s, 2);
            sc += __shfl_xor_sync(0xffffffffu, sc, 2);
            s  += __shfl_xor_sync(0xffffffffu, s, 4);
            sc += __shfl_xor_sync(0xffffffffu, sc, 4);
            if (li == 0 && act) { sW[j] = s; sWC[j] = sc; }
        }
        for (int j = 64; j < n; j++) {   // fallback (not taken for this data)
            int col = g_perm[p0 + j];
            float2 rk = __half22float2(rkh2[col * 32 + lane]);
            float2 iv = __half22float2(icfh2[col * 32 + lane]);
            float s  = warpsum(rk.x * sU[2 * lane] + rk.y * sU[2 * lane + 1]);
            float sc = warpsum(iv.x * sUC[2 * lane] + iv.y * sUC[2 * lane + 1]);
            if (lane == 0) { g_p[pb + j] = s; g_pcf[pb + j] = sc; }
        }
        __syncwarp();
        // ---- pass 2: weights = exp(sigmoid(dot)) (max-free, exact) ----
        float se = 0.f, sec = 0.f;
        if (lane < nin) {
            float e  = __expf(sigmoidf(sW[lane]));
            float ec = __expf(sigmoidf(sWC[lane]));
            sW[lane] = e; sWC[lane] = ec; se += e; sec += ec;
        }
        if (lane + 32 < nin) {
            float e  = __expf(sigmoidf(sW[lane + 32]));
            float ec = __expf(sigmoidf(sWC[lane + 32]));
            sW[lane + 32] = e; sWC[lane + 32] = ec; se += e; sec += ec;
        }
        for (int j = 64 + lane; j < n; j += 32) {
            float e  = __expf(sigmoidf(g_p[pb + j]));
            float ec = __expf(sigmoidf(g_pcf[pb + j]));
            g_p[pb + j] = e; g_pcf[pb + j] = ec;
            se += e; sec += ec;
        }
        se = warpsum(se); sec = warpsum(sec);
        float inv = 1.f / se, invc = 1.f / sec;
        __syncwarp();
        // ---- pass 3: weighted accumulation (half rows) ----
        float2 A = make_float2(0.f, 0.f), B = make_float2(0.f, 0.f);
        for (int j = 0; j < nin; j++) {
            int col = sCol[j];
            float wp = sW[j] * inv, wc = sWC[j] * invc;
            float2 gv = __half22float2(kgh2[col * 32 + lane]);
            float2 iv = __half22float2(icfh2[col * 32 + lane]);
            A.x += wp * gv.x; A.y += wp * gv.y;
            B.x += wc * iv.x; B.y += wc * iv.y;
        }
        for (int j = 64; j < n; j++) {
            float wp = g_p[pb + j] * inv, wc = g_pcf[pb + j] * invc;
            int col = g_perm[p0 + j];
            float2 gv = __half22float2(kgh2[col * 32 + lane]);
            float2 iv = __half22float2(icfh2[col * 32 + lane]);
            A.x += wp * gv.x; A.y += wp * gv.y;
            B.x += wc * iv.x; B.y += wc * iv.y;
        }
        float ss = warpsum(A.x * A.x + A.y * A.y);
        float i1 = 1.f / fmaxf(sqrtf(ss), 1e-12f);
        ss = warpsum(B.x * B.x + B.y * B.y);
        float i2 = 1.f / fmaxf(sqrtf(ss), 1e-12f);
        ud.x = A.x * i1; ud.y = A.y * i1;
        cd.x = B.x * i2; cd.y = B.y * i2;
        if (it < 2) {
            __syncwarp();
            sU[2 * lane] = ud.x;  sU[2 * lane + 1] = ud.y;
            sUC[2 * lane] = cd.x; sUC[2 * lane + 1] = cd.y;
            __syncwarp();
        }
    }

    udst2[u * 32 + lane] = ud;
    ucfdst2[u * 32 + lane] = cd;
    int o1 = NE * 32 + u * 32 + lane;
    float2 o = out2[o1]; o.x += ud.x; o.y += ud.y; out2[o1] = o;
    int o2 = (NE + NU) * 32 + u * 32 + lane;
    o = out2[o2]; o.x += cd.x; o.y += cd.y; out2[o2] = o;
}

extern "C" void kernel_launch(void* const* d_in, const int* in_sizes, int n_in,
                              void* d_out, int out_size) {
    const float* user_emb = (const float*)d_in[0];
    const float* entity_emb = (const float*)d_in[1];
    const float* emb_cf = (const float*)d_in[2];
    const float* relw = (const float*)d_in[3];
    const float* W1 = (const float*)d_in[4];
    const float* B1 = (const float*)d_in[5];
    const float* W2 = (const float*)d_in[6];
    const float* B2 = (const float*)d_in[7];
    const int* eidx = (const int*)d_in[8];
    const int* etype = (const int*)d_in[9];
    const int* imat = (const int*)d_in[10];
    float* out = (float*)d_out;

    const int* heads = eidx;
    const int* tails = eidx + NEDGE;
    const float* ucf_ext = emb_cf;
    const int2* imat2 = (const int2*)imat;

    k_init<<<2048, 256>>>(user_emb, entity_emb, emb_cf, W1, W2, out);
    k_count<<<3907, 256>>>(heads, imat2);
    k_scan1<<<SCAN_NBLK, SCAN_BLK>>>();
    k_scanB<<<SCAN_NBLK, SCAN_BLK>>>();
    k_scatter<<<3907, 256>>>(heads, tails, etype, imat2);

    for (int h = 0; h < 2; h++) {
        k_entity<<<NE / 8, 256>>>(entity_emb, h, relw,
                                  B1 + h * DM, B2 + h * DM, out);
        k_useritem<<<USER_BLOCKS + ITEM_BLOCKS, 256>>>(user_emb, ucf_ext, h, out);
    }
    (void)in_sizes; (void)n_in; (void)out_size;
}

// round 17
// speedup vs baseline: 1.0052x; 1.0052x over previous
#include <cuda_runtime.h>
#include <cuda_fp16.h>
#include <math.h>

#define NU 100000
#define NI 50000
#define NE 120000
#define NR 32
#define DM 64
#define NEDGE 1000000
#define NCF 1000000

#define SEG_U 120000
#define SEG_I 220000
#define NSEG 270000
#define SCAN_N 270001
#define SCAN_BLK 1024
#define SCAN_NBLK 264

#define USER_BLOCKS 12500         // NU/8
#define ITEM_BLOCKS 6250          // NI/8

__device__ int   g_cnt[SCAN_NBLK * SCAN_BLK];
__device__ int   g_off[SCAN_NBLK * SCAN_BLK + 1];
__device__ int   g_perm[NEDGE + 2 * NCF];   // PAYLOADS: entity=(tail<<5)|type, user=col, item=row
__device__ int   g_bsum[SCAN_BLK];

__device__ float g_entA[NE * DM];
__device__ float g_entB[NE * DM];
__device__ float g_u[NU * DM];
__device__ float g_ucf0[NU * DM];
__device__ float g_ucf1[NU * DM];

// transposed weight matrices (Wt[k*64+d] = W[d*64+k]), per hop
__device__ float g_W1t[2][DM * DM];
__device__ float g_W2t[2][DM * DM];

// half item tables gathered by k_useritem (col < NI only); icf double-buffered
__device__ __half g_relkg_h[NI * DM];
__device__ __half g_kg_h[NI * DM];
__device__ __half g_icf_h[2][NI * DM];

__device__ __forceinline__ float warpsum(float v) {
    #pragma unroll
    for (int o = 16; o; o >>= 1) v += __shfl_xor_sync(0xffffffffu, v, o);
    return v;
}
__device__ __forceinline__ float lrelu(float x) { return x > 0.f ? x : 0.01f * x; }
__device__ __forceinline__ float sigmoidf(float x) { return 1.f / (1.f + __expf(-x)); }

// init: out = concat(...) + zero counters + seed icf_h[0] + transpose weights
__global__ void k_init(const float* __restrict__ ue, const float* __restrict__ ee,
                       const float* __restrict__ cf,
                       const float* __restrict__ W1, const float* __restrict__ W2,
                       float* __restrict__ out) {
    const int total = (NE + NU + NU + NI) * DM;
    for (int i = blockIdx.x * blockDim.x + threadIdx.x; i < total; i += gridDim.x * blockDim.x) {
        if (i < SCAN_NBLK * SCAN_BLK) g_cnt[i] = 0;
        if (i < 2 * DM * DM) {              // transpose both hops' W1/W2
            int h = i >> 12, r = i & 4095;
            int d = r >> 6, k = r & 63;
            g_W1t[h][k * 64 + d] = W1[h * 4096 + d * 64 + k];
            g_W2t[h][k * 64 + d] = W2[h * 4096 + d * 64 + k];
        }
        float v;
        if (i < NE * DM)                   v = ee[i];
        else if (i < (NE + NU) * DM)       v = ue[i - NE * DM];
        else if (i < (NE + 2 * NU) * DM)   v = cf[i - (NE + NU) * DM];
        else {
            int d = i - (NE + 2 * NU) * DM;
            v = cf[NU * DM + d];
            g_icf_h[0][d] = __float2half(v);
        }
        out[i] = v;
    }
}

__global__ void k_count(const int* __restrict__ heads, const int2* __restrict__ imat2) {
    for (int i = blockIdx.x * blockDim.x + threadIdx.x; i < NEDGE; i += gridDim.x * blockDim.x) {
        int2 rc = imat2[i];
        atomicAdd(&g_cnt[heads[i]], 1);
        atomicAdd(&g_cnt[SEG_U + rc.x], 1);
        atomicAdd(&g_cnt[SEG_I + rc.y], 1);
    }
}

__global__ void k_scan1() {
    __shared__ int sh[SCAN_BLK];
    int t = threadIdx.x;
    int i = blockIdx.x * SCAN_BLK + t;
    sh[t] = (i < SCAN_N) ? g_cnt[i] : 0;
    __syncthreads();
    for (int s = SCAN_BLK / 2; s > 0; s >>= 1) {
        if (t < s) sh[t] += sh[t + s];
        __syncthreads();
    }
    if (t == 0) g_bsum[blockIdx.x] = sh[0];
}

// fused scan2+scan3
__global__ void k_scanB() {
    __shared__ int sb[SCAN_BLK];
    __shared__ int sh[SCAN_BLK];
    int t = threadIdx.x;
    int v0 = (t < SCAN_NBLK) ? g_bsum[t] : 0;
    sb[t] = v0;
    __syncthreads();
    for (int d = 1; d < SCAN_BLK; d <<= 1) {
        int x = (t >= d) ? sb[t - d] : 0;
        __syncthreads();
        sb[t] += x;
        __syncthreads();
    }
    int boff = (blockIdx.x == 0) ? 0 : sb[blockIdx.x - 1];

    int i = blockIdx.x * SCAN_BLK + t;
    int v = (i < SCAN_N) ? g_cnt[i] : 0;
    sh[t] = v;
    __syncthreads();
    for (int d = 1; d < SCAN_BLK; d <<= 1) {
        int x = (t >= d) ? sh[t - d] : 0;
        __syncthreads();
        sh[t] += x;
        __syncthreads();
    }
    if (i < SCAN_N) g_off[i] = boff + sh[t] - v;
}

// in-place cursors: atomicAdd on g_off[seg] hands out slots directly.
// Post-scatter: g_off[s] == end of segment s; p0 = s ? g_off[s-1] : 0.
__global__ void k_scatter(const int* __restrict__ heads, const int* __restrict__ tails,
                          const int* __restrict__ etype, const int2* __restrict__ imat2) {
    for (int i = blockIdx.x * blockDim.x + threadIdx.x; i < NEDGE; i += gridDim.x * blockDim.x) {
        int h = heads[i];
        int p = atomicAdd(&g_off[h], 1);
        g_perm[p] = (tails[i] << 5) | etype[i];
        int2 rc = imat2[i];
        p = atomicAdd(&g_off[SEG_U + rc.x], 1);
        g_perm[p] = rc.y;
        p = atomicAdd(&g_off[SEG_I + rc.y], 1);
        g_perm[p] = rc.x;
    }
}

// entity aggregation: warp-per-entity, LOW-SMEM (s_rel only, 8KB -> full occupancy).
__global__ void k_entity(const float* __restrict__ ext_ent, int hop,
                         const float* __restrict__ relw,
                         const float* __restrict__ b1, const float* __restrict__ b2,
                         float* __restrict__ out) {
    __shared__ float s_rel[NR * DM];
    int t = threadIdx.x;
    for (int i = t; i < NR * DM; i += blockDim.x) s_rel[i] = relw[i];
    __syncthreads();

    const float* entin = hop ? g_entB : ext_ent;
    float* entout      = hop ? g_entA : g_entB;
    const float* Wt1 = g_W1t[hop];
    const float* Wt2 = g_W2t[hop];

    int lane = t & 31;
    int e = blockIdx.x * (blockDim.x >> 5) + (t >> 5);
    if (e >= NE) return;
    int p1 = g_off[e];
    int p0 = e ? g_off[e - 1] : 0;
    bool eItem = e < NI;

    float a10 = 0, a11 = 0, a20 = 0, a21 = 0, ar0 = 0, ar1 = 0;
    int nc = 0;
    for (int p = p0; p < p1; p++) {
        int packed = g_perm[p];
        int tl = packed >> 5, ty = packed & 31;
        float r0 = s_rel[ty * 64 + lane], r1 = s_rel[ty * 64 + 32 + lane];
        float t0 = entin[tl * 64 + lane], t1 = entin[tl * 64 + 32 + lane];
        bool cross = eItem != (tl < NI);
        if (cross) { a10 += t0 * r0; a11 += t1 * r1; nc++; }
        else       { a20 += t0 + r0; a21 += t1 + r1; }
        ar0 += r0; ar1 += r1;
    }
    int n = p1 - p0;

    if (eItem) {
        float dn = 1.f / fmaxf((float)n, 1.f);
        float e0 = entin[e * 64 + lane], e1 = entin[e * 64 + 32 + lane];
        g_relkg_h[e * 64 + lane]      = __float2half((ar0 * dn) * e0);
        g_relkg_h[e * 64 + 32 + lane] = __float2half((ar1 * dn) * e1);
        g_kg_h[e * 64 + lane]         = __float2half(e0);
        g_kg_h[e * 64 + 32 + lane]    = __float2half(e1);
    }

    float i1 = 1.f / fmaxf((float)nc, 1.f);
    float i2 = 1.f / fmaxf((float)(n - nc), 1.f);
    a10 *= i1; a11 *= i1; a20 *= i2; a21 *= i2;

    float o10 = __ldg(&b1[lane]), o11 = __ldg(&b1[lane + 32]);
    float o20 = __ldg(&b2[lane]), o21 = __ldg(&b2[lane + 32]);
    #pragma unroll
    for (int k = 0; k < 64; k++) {
        float a1 = __shfl_sync(0xffffffffu, (k < 32) ? a10 : a11, k & 31);
        float a2 = __shfl_sync(0xffffffffu, (k < 32) ? a20 : a21, k & 31);
        o10 += a1 * __ldg(&Wt1[k * 64 + lane]);
        o11 += a1 * __ldg(&Wt1[k * 64 + 32 + lane]);
        o20 += a2 * __ldg(&Wt2[k * 64 + lane]);
        o21 += a2 * __ldg(&Wt2[k * 64 + 32 + lane]);
    }
    float v0 = 0.5f * (lrelu(o10) + lrelu(o20));
    float v1 = 0.5f * (lrelu(o11) + lrelu(o21));
    float ss = warpsum(v0 * v0 + v1 * v1);
    float inv = 1.f / fmaxf(sqrtf(ss), 1e-12f);
    v0 *= inv; v1 *= inv;
    entout[e * 64 + lane] = v0;
    entout[e * 64 + 32 + lane] = v1;
    out[e * 64 + lane] += v0;
    out[e * 64 + 32 + lane] += v1;
}

// fused USER + ITEM kernel. User path: single-loop softmax-attention
// (pass1+2+3 merged; weights computed on the fly, no scalar storage).
__global__ void __launch_bounds__(256) k_useritem(
        const float* __restrict__ ext_user, const float* __restrict__ ext_ucf,
        int hop, float* __restrict__ out)
{
    __shared__ __align__(16) float sm[8 * 192];   // per warp: U64|UC64|COL64

    int w = threadIdx.x >> 5, lane = threadIdx.x & 31;

    if (blockIdx.x >= USER_BLOCKS) {
        // ---------------- item path ----------------
        const float2* ucfin2 = (const float2*)(hop ? g_ucf0 : ext_ucf);
        float2* out2 = (float2*)out;
        int c = (blockIdx.x - USER_BLOCKS) * 8 + w;
        if (c >= NI) return;
        int p1 = g_off[SEG_I + c];
        int p0 = g_off[SEG_I + c - 1];
        float2 acc = make_float2(0.f, 0.f);
        for (int p = p0; p < p1; p++) {
            int row = g_perm[p];
            float2 v = ucfin2[row * 32 + lane];
            acc.x += v.x; acc.y += v.y;
        }
        float dn = 1.f / fmaxf((float)(p1 - p0), 1.f);
        acc.x *= dn; acc.y *= dn;
        float ss = warpsum(acc.x * acc.x + acc.y * acc.y);
        float inv = 1.f / fmaxf(sqrtf(ss), 1e-12f);
        acc.x *= inv; acc.y *= inv;
        ((__half2*)g_icf_h[(hop + 1) & 1])[c * 32 + lane] = __floats2half2_rn(acc.x, acc.y);
        int ob = (NE + 2 * NU) * 32 + c * 32 + lane;
        float2 o = out2[ob];
        o.x += acc.x; o.y += acc.y;
        out2[ob] = o;
        return;
    }

    // ---------------- user path (single-loop) ----------------
    const __half* icf_tab = g_icf_h[hop & 1];
    const uint4* rkh4  = (const uint4*)g_relkg_h;   // 8 uint4 (= 64 halves) per row
    const uint4* kgh4  = (const uint4*)g_kg_h;
    const uint4* icfh4 = (const uint4*)icf_tab;
    const float* usrc   = hop ? g_u    : ext_user;
    const float* ucfsrc = hop ? g_ucf0 : ext_ucf;
    float4* udst4   = (float4*)g_u;
    float4* ucfdst4 = (float4*)(hop ? g_ucf1 : g_ucf0);
    float2* udst2   = (float2*)g_u;
    float2* ucfdst2 = (float2*)(hop ? g_ucf1 : g_ucf0);
    float4* out4    = (float4*)out;

    int u = blockIdx.x * 8 + w;
    if (u >= NU) return;

    float* sU  = sm + w * 192;
    float* sUC = sU + 64;
    int*   sCol = (int*)(sU + 128);

    int p1 = g_off[SEG_U + u];
    int p0 = g_off[SEG_U + u - 1];
    int n  = p1 - p0;
    if (n == 0) {
        float2 z = make_float2(0.f, 0.f);
        udst2[u * 32 + lane] = z;
        ucfdst2[u * 32 + lane] = z;
        return;
    }
    int nin = n < 64 ? n : 64;

    sU[lane]       = usrc[u * 64 + lane];
    sU[32 + lane]  = usrc[u * 64 + 32 + lane];
    sUC[lane]      = ucfsrc[u * 64 + lane];
    sUC[32 + lane] = ucfsrc[u * 64 + 32 + lane];
    if (lane < nin)      sCol[lane]      = g_perm[p0 + lane];
    if (lane + 32 < nin) sCol[lane + 32] = g_perm[p0 + lane + 32];
    __syncwarp();

    int li = lane & 7, g = lane >> 3;   // 4 groups x 8 lanes; lane covers dims 8li..8li+7
    float Af[8], Bf[8];

    for (int it = 0; it < 3; it++) {
        #pragma unroll
        for (int k = 0; k < 8; k++) { Af[k] = 0.f; Bf[k] = 0.f; }
        float sumE = 0.f, sumEC = 0.f;
        float4 u0 = *(const float4*)(sU + 8 * li);
        float4 u1 = *(const float4*)(sU + 8 * li + 4);
        float4 c0 = *(const float4*)(sUC + 8 * li);
        float4 c1 = *(const float4*)(sUC + 8 * li + 4);

        for (int jb = 0; jb < n; jb += 4) {
            int j = jb + g;
            bool act = j < n;
            int col = act ? ((j < 64) ? sCol[j] : g_perm[p0 + j]) : 0;
            uint4 ra = rkh4[col * 8 + li];
            uint4 ba = icfh4[col * 8 + li];
            uint4 ga = kgh4[col * 8 + li];
            float2 r0 = __half22float2(*(const __half2*)&ra.x);
            float2 r1 = __half22float2(*(const __half2*)&ra.y);
            float2 r2 = __half22float2(*(const __half2*)&ra.z);
            float2 r3 = __half22float2(*(const __half2*)&ra.w);
            float2 b0 = __half22float2(*(const __half2*)&ba.x);
            float2 b1 = __half22float2(*(const __half2*)&ba.y);
            float2 b2 = __half22float2(*(const __half2*)&ba.z);
            float2 b3 = __half22float2(*(const __half2*)&ba.w);
            float s  = r0.x*u0.x + r0.y*u0.y + r1.x*u0.z + r1.y*u0.w
                     + r2.x*u1.x + r2.y*u1.y + r3.x*u1.z + r3.y*u1.w;
            float sc = b0.x*c0.x + b0.y*c0.y + b1.x*c0.z + b1.y*c0.w
                     + b2.x*c1.x + b2.y*c1.y + b3.x*c1.z + b3.y*c1.w;
            s  += __shfl_xor_sync(0xffffffffu, s, 1);
            sc += __shfl_xor_sync(0xffffffffu, sc, 1);
            s  += __shfl_xor_sync(0xffffffffu, s, 2);
            sc += __shfl_xor_sync(0xffffffffu, sc, 2);
            s  += __shfl_xor_sync(0xffffffffu, s, 4);
            sc += __shfl_xor_sync(0xffffffffu, sc, 4);
            // group leader computes weights (4 active lanes -> 1 warp-instr per exp)
            float e = 0.f, ec = 0.f;
            if (li == 0 && act) {
                e  = __expf(sigmoidf(s));
                ec = __expf(sigmoidf(sc));
            }
            e  = __shfl_sync(0xffffffffu, e,  lane & 24);
            ec = __shfl_sync(0xffffffffu, ec, lane & 24);
            sumE += e; sumEC += ec;
            float2 g0 = __half22float2(*(const __half2*)&ga.x);
            float2 g1 = __half22float2(*(const __half2*)&ga.y);
            float2 g2 = __half22float2(*(const __half2*)&ga.z);
            float2 g3 = __half22float2(*(const __half2*)&ga.w);
            Af[0] += e * g0.x; Af[1] += e * g0.y;
            Af[2] += e * g1.x; Af[3] += e * g1.y;
            Af[4] += e * g2.x; Af[5] += e * g2.y;
            Af[6] += e * g3.x; Af[7] += e * g3.y;
            Bf[0] += ec * b0.x; Bf[1] += ec * b0.y;
            Bf[2] += ec * b1.x; Bf[3] += ec * b1.y;
            Bf[4] += ec * b2.x; Bf[5] += ec * b2.y;
            Bf[6] += ec * b3.x; Bf[7] += ec * b3.y;
        }
        // cross-group accumulator reduction (lanes with equal li end up with full sums)
        #pragma unroll
        for (int k = 0; k < 8; k++) {
            Af[k] += __shfl_xor_sync(0xffffffffu, Af[k], 8);
            Af[k] += __shfl_xor_sync(0xffffffffu, Af[k], 16);
            Bf[k] += __shfl_xor_sync(0xffffffffu, Bf[k], 8);
            Bf[k] += __shfl_xor_sync(0xffffffffu, Bf[k], 16);
        }
        // group sums: lanes within a group hold identical sumE -> 2 shfls suffice
        sumE  += __shfl_xor_sync(0xffffffffu, sumE, 8);
        sumE  += __shfl_xor_sync(0xffffffffu, sumE, 16);
        sumEC += __shfl_xor_sync(0xffffffffu, sumEC, 8);
        sumEC += __shfl_xor_sync(0xffffffffu, sumEC, 16);
        float invE = 1.f / sumE, invEC = 1.f / sumEC;
        float ssA = 0.f, ssB = 0.f;
        #pragma unroll
        for (int k = 0; k < 8; k++) {
            float a = Af[k] * invE;  Af[k] = a; ssA += a * a;
            float b = Bf[k] * invEC; Bf[k] = b; ssB += b * b;
        }
        // dim-sum within group (each lane covers 8 distinct dims; groups duplicate)
        ssA += __shfl_xor_sync(0xffffffffu, ssA, 1);
        ssA += __shfl_xor_sync(0xffffffffu, ssA, 2);
        ssA += __shfl_xor_sync(0xffffffffu, ssA, 4);
        ssB += __shfl_xor_sync(0xffffffffu, ssB, 1);
        ssB += __shfl_xor_sync(0xffffffffu, ssB, 2);
        ssB += __shfl_xor_sync(0xffffffffu, ssB, 4);
        float i1n = 1.f / fmaxf(sqrtf(ssA), 1e-12f);
        float i2n = 1.f / fmaxf(sqrtf(ssB), 1e-12f);
        #pragma unroll
        for (int k = 0; k < 8; k++) { Af[k] *= i1n; Bf[k] *= i2n; }
        if (it < 2) {
            __syncwarp();
            if (g == 0) {
                #pragma unroll
                for (int k = 0; k < 8; k++) {
                    sU[8 * li + k]  = Af[k];
                    sUC[8 * li + k] = Bf[k];
                }
            }
            __syncwarp();
        }
    }

    if (g == 0) {
        float4 a0 = make_float4(Af[0], Af[1], Af[2], Af[3]);
        float4 a1 = make_float4(Af[4], Af[5], Af[6], Af[7]);
        float4 b0 = make_float4(Bf[0], Bf[1], Bf[2], Bf[3]);
        float4 b1 = make_float4(Bf[4], Bf[5], Bf[6], Bf[7]);
        udst4[u * 16 + 2 * li]     = a0;
        udst4[u * 16 + 2 * li + 1] = a1;
        ucfdst4[u * 16 + 2 * li]     = b0;
        ucfdst4[u * 16 + 2 * li + 1] = b1;
        int o1 = NE * 16 + u * 16 + 2 * li;
        float4 o = out4[o1];
        o.x += a0.x; o.y += a0.y; o.z += a0.z; o.w += a0.w;
        out4[o1] = o;
        o = out4[o1 + 1];
        o.x += a1.x; o.y += a1.y; o.z += a1.z; o.w += a1.w;
        out4[o1 + 1] = o;
        int o2 = (NE + NU) * 16 + u * 16 + 2 * li;
        o = out4[o2];
        o.x += b0.x; o.y += b0.y; o.z += b0.z; o.w += b0.w;
        out4[o2] = o;
        o = out4[o2 + 1];
        o.x += b1.x; o.y += b1.y; o.z += b1.z; o.w += b1.w;
        out4[o2 + 1] = o;
    }
}

extern "C" void kernel_launch(void* const* d_in, const int* in_sizes, int n_in,
                              void* d_out, int out_size) {
    const float* user_emb = (const float*)d_in[0];
    const float* entity_emb = (const float*)d_in[1];
    const float* emb_cf = (const float*)d_in[2];
    const float* relw = (const float*)d_in[3];
    const float* W1 = (const float*)d_in[4];
    const float* B1 = (const float*)d_in[5];
    const float* W2 = (const float*)d_in[6];
    const float* B2 = (const float*)d_in[7];
    const int* eidx = (const int*)d_in[8];
    const int* etype = (const int*)d_in[9];
    const int* imat = (const int*)d_in[10];
    float* out = (float*)d_out;

    const int* heads = eidx;
    const int* tails = eidx + NEDGE;
    const float* ucf_ext = emb_cf;
    const int2* imat2 = (const int2*)imat;

    k_init<<<2048, 256>>>(user_emb, entity_emb, emb_cf, W1, W2, out);
    k_count<<<3907, 256>>>(heads, imat2);
    k_scan1<<<SCAN_NBLK, SCAN_BLK>>>();
    k_scanB<<<SCAN_NBLK, SCAN_BLK>>>();
    k_scatter<<<3907, 256>>>(heads, tails, etype, imat2);

    for (int h = 0; h < 2; h++) {
        k_entity<<<NE / 8, 256>>>(entity_emb, h, relw,
                                  B1 + h * DM, B2 + h * DM, out);
        k_useritem<<<USER_BLOCKS + ITEM_BLOCKS, 256>>>(user_emb, ucf_ext, h, out);
    }
    (void)in_sizes; (void)n_in; (void)out_size;
}